// round 15
// baseline (speedup 1.0000x reference)
#include <cuda_runtime.h>

// PrimitiveGate: apply complex 2x2 gate to qubit axis 12 of a 23-qubit state,
// batch 4. State layout: (DIM, BATCH) float32, re and im planes separate.
// Output: (2, DIM, BATCH) float32 -> [out_re | out_im].
//
// Axis 12 of 23 (axis 0 = MSB) -> bit 10 of the dim index.
// BATCH=4 contiguous floats per dim index -> one float4 per (dim, batch-row).
//
// FINAL — HBM-roofline kernel at the B300 mixed-R/W streaming ceiling.
// 536 MB irreducible traffic at ~6.5 TB/s (82-83% of 8 TB/s spec; residual
// is DRAM R/W bus-turnaround + refresh, not SM-addressable).
//
// Complete session lever matrix (14 rounds, every direction bracketed):
//   .cs streaming hints      -> neutral   (L2 policy not the limiter)
//   ILP=2 / MLP=8 per thread -> regressed (occ -17%, DRAM -2.6%)
//   persistent grid-stride   -> regressed (DRAM -6%: loop-carried deps
//                               throttle per-warp MLP; short dependency-free
//                               CTAs are the optimal DRAM-queue feeder)
//   block-size bowl: persistent << 64 < 512 ~ 256 < **128** (minimum)
//     TPB=128: kernel 73.5-74.5us, DRAM 81.8-82.7%, harness 81.89-82.27us
//     across R10/R12/R13/R14 — the measured optimum, 8 reproductions.
// One pair per thread, 32 regs, ~82% occ, exact float4 coalescing,
// 100% sector efficiency, MLP=4 front-batched dependency-free loads.

#define N_QUBITS 23
#define TARGET_BIT 10            // N_QUBITS - 1 - TARGET_Q(12)
#define DIM (1u << N_QUBITS)     // 8388608
#define NPAIRS (DIM >> 1)        // 4194304
#define LOWMASK ((1u << TARGET_BIT) - 1u)
#define TPB 128

__global__ void __launch_bounds__(TPB)
gate_kernel(const float4* __restrict__ sre,
            const float4* __restrict__ sim,
            const float*  __restrict__ mre,
            const float*  __restrict__ mim,
            float4* __restrict__ out)
{
    unsigned p = blockIdx.x * (unsigned)TPB + threadIdx.x;

    // i0: insert a 0 at bit TARGET_BIT; i1 = i0 | (1<<TARGET_BIT)
    unsigned i0 = ((p & ~LOWMASK) << 1) | (p & LOWMASK);
    unsigned i1 = i0 | (1u << TARGET_BIT);

    // Front-batched independent streaming loads (MLP = 4), evict-first
    float4 a_re = __ldcs(&sre[i0]);
    float4 b_re = __ldcs(&sre[i1]);
    float4 a_im = __ldcs(&sim[i0]);
    float4 b_im = __ldcs(&sim[i1]);

    // 2x2 complex gate, row-major (tiny, hot in L1 — normal loads)
    float m00r = __ldg(&mre[0]), m01r = __ldg(&mre[1]);
    float m10r = __ldg(&mre[2]), m11r = __ldg(&mre[3]);
    float m00i = __ldg(&mim[0]), m01i = __ldg(&mim[1]);
    float m10i = __ldg(&mim[2]), m11i = __ldg(&mim[3]);

    float4 o0r, o0i, o1r, o1i;

#define LANE(f)                                                                 \
    do {                                                                        \
        float s0r = a_re.f, s0i = a_im.f, s1r = b_re.f, s1i = b_im.f;           \
        o0r.f = fmaf(m00r, s0r, fmaf(-m00i, s0i, fmaf(m01r, s1r, -m01i * s1i)));\
        o0i.f = fmaf(m00r, s0i, fmaf( m00i, s0r, fmaf(m01r, s1i,  m01i * s1r)));\
        o1r.f = fmaf(m10r, s0r, fmaf(-m10i, s0i, fmaf(m11r, s1r, -m11i * s1i)));\
        o1i.f = fmaf(m10r, s0i, fmaf( m10i, s0r, fmaf(m11r, s1i,  m11i * s1r)));\
    } while (0)

    LANE(x); LANE(y); LANE(z); LANE(w);
#undef LANE

    // out_re plane at [0, DIM), out_im plane at [DIM, 2*DIM) (in float4 units)
    // Streaming stores: full-line coalesced, evict-first.
    __stcs(&out[i0],       o0r);
    __stcs(&out[i1],       o1r);
    __stcs(&out[DIM + i0], o0i);
    __stcs(&out[DIM + i1], o1i);
}

extern "C" void kernel_launch(void* const* d_in, const int* in_sizes, int n_in,
                              void* d_out, int out_size)
{
    const float4* sre = (const float4*)d_in[0];
    const float4* sim = (const float4*)d_in[1];
    const float*  mre = (const float*)d_in[2];
    const float*  mim = (const float*)d_in[3];
    float4* out = (float4*)d_out;

    dim3 grid(NPAIRS / TPB);  // 32768 blocks, exact
    gate_kernel<<<grid, TPB>>>(sre, sim, mre, mim, out);
}

// round 16
// speedup vs baseline: 1.0035x; 1.0035x over previous
#include <cuda_runtime.h>

// PrimitiveGate: apply complex 2x2 gate to qubit axis 12 of a 23-qubit state,
// batch 4. State layout: (DIM, BATCH) float32, re and im planes separate.
// Output: (2, DIM, BATCH) float32 -> [out_re | out_im].
//
// Axis 12 of 23 (axis 0 = MSB) -> bit 10 of the dim index.
// BATCH=4 contiguous floats per dim index -> one float4 per (dim, batch-row).
//
// FINAL — HBM-roofline kernel at the B300 mixed-R/W streaming ceiling.
// 536 MB irreducible traffic at ~6.5 TB/s (82-83% of 8 TB/s spec; residual
// is DRAM R/W bus-turnaround + refresh, not SM-addressable).
//
// Complete session lever matrix (15 rounds, every direction bracketed):
//   .cs streaming hints      -> neutral   (L2 policy not the limiter)
//   ILP=2 / MLP=8 per thread -> regressed (occ -17%, DRAM -2.6%)
//   persistent grid-stride   -> regressed (DRAM -6%: loop-carried deps
//                               throttle per-warp MLP; short dependency-free
//                               CTAs are the optimal DRAM-queue feeder)
//   block-size bowl: persistent << 64 < 512 ~ 256 < **128** (minimum)
//     TPB=128: kernel 73.5-74.6us, DRAM 81.2-82.7%, harness 81.89-82.27us
//     across 9 reproductions — the measured optimum.
// One pair per thread, 32 regs, ~82-85% occ, exact float4 coalescing,
// 100% sector efficiency, MLP=4 front-batched dependency-free loads.

#define N_QUBITS 23
#define TARGET_BIT 10            // N_QUBITS - 1 - TARGET_Q(12)
#define DIM (1u << N_QUBITS)     // 8388608
#define NPAIRS (DIM >> 1)        // 4194304
#define LOWMASK ((1u << TARGET_BIT) - 1u)
#define TPB 128

__global__ void __launch_bounds__(TPB)
gate_kernel(const float4* __restrict__ sre,
            const float4* __restrict__ sim,
            const float*  __restrict__ mre,
            const float*  __restrict__ mim,
            float4* __restrict__ out)
{
    unsigned p = blockIdx.x * (unsigned)TPB + threadIdx.x;

    // i0: insert a 0 at bit TARGET_BIT; i1 = i0 | (1<<TARGET_BIT)
    unsigned i0 = ((p & ~LOWMASK) << 1) | (p & LOWMASK);
    unsigned i1 = i0 | (1u << TARGET_BIT);

    // Front-batched independent streaming loads (MLP = 4), evict-first
    float4 a_re = __ldcs(&sre[i0]);
    float4 b_re = __ldcs(&sre[i1]);
    float4 a_im = __ldcs(&sim[i0]);
    float4 b_im = __ldcs(&sim[i1]);

    // 2x2 complex gate, row-major (tiny, hot in L1 — normal loads)
    float m00r = __ldg(&mre[0]), m01r = __ldg(&mre[1]);
    float m10r = __ldg(&mre[2]), m11r = __ldg(&mre[3]);
    float m00i = __ldg(&mim[0]), m01i = __ldg(&mim[1]);
    float m10i = __ldg(&mim[2]), m11i = __ldg(&mim[3]);

    float4 o0r, o0i, o1r, o1i;

#define LANE(f)                                                                 \
    do {                                                                        \
        float s0r = a_re.f, s0i = a_im.f, s1r = b_re.f, s1i = b_im.f;           \
        o0r.f = fmaf(m00r, s0r, fmaf(-m00i, s0i, fmaf(m01r, s1r, -m01i * s1i)));\
        o0i.f = fmaf(m00r, s0i, fmaf( m00i, s0r, fmaf(m01r, s1i,  m01i * s1r)));\
        o1r.f = fmaf(m10r, s0r, fmaf(-m10i, s0i, fmaf(m11r, s1r, -m11i * s1i)));\
        o1i.f = fmaf(m10r, s0i, fmaf( m10i, s0r, fmaf(m11r, s1i,  m11i * s1r)));\
    } while (0)

    LANE(x); LANE(y); LANE(z); LANE(w);
#undef LANE

    // out_re plane at [0, DIM), out_im plane at [DIM, 2*DIM) (in float4 units)
    // Streaming stores: full-line coalesced, evict-first.
    __stcs(&out[i0],       o0r);
    __stcs(&out[i1],       o1r);
    __stcs(&out[DIM + i0], o0i);
    __stcs(&out[DIM + i1], o1i);
}

extern "C" void kernel_launch(void* const* d_in, const int* in_sizes, int n_in,
                              void* d_out, int out_size)
{
    const float4* sre = (const float4*)d_in[0];
    const float4* sim = (const float4*)d_in[1];
    const float*  mre = (const float*)d_in[2];
    const float*  mim = (const float*)d_in[3];
    float4* out = (float4*)d_out;

    dim3 grid(NPAIRS / TPB);  // 32768 blocks, exact
    gate_kernel<<<grid, TPB>>>(sre, sim, mre, mim, out);
}